// round 1
// baseline (speedup 1.0000x reference)
#include <cuda_runtime.h>
#include <math.h>

// Problem constants
constexpr int Nn = 100000;
constexpr int Ee = 1600000;
constexpr int Hh = 128;
constexpr int Mm = 256;
constexpr int Ll = 6;
constexpr int Gg = 512;

// ---------------- scratch (device globals; no allocation allowed) ----------
__device__ float g_h[Nn * Hh];       // node features / residual
__device__ float g_xw[Nn * Hh];      // conv GEMM output (pre-aggregation)
__device__ float g_agg[Nn * Hh];     // aggregated + normalized activations
__device__ float g_t[Nn * Mm];       // MLP hidden
__device__ int   g_deg[Nn];
__device__ int   g_cursor[Nn];
__device__ int   g_rowoff[Nn + 1];
__device__ float g_dinv[Nn];
__device__ int   g_gcount[Gg];
__device__ int   g_gstart[Gg + 1];

struct __align__(8) EdgeT { int src; float w; };
__device__ EdgeT g_edges[Ee];

// ---------------- setup kernels -------------------------------------------
__global__ void zero_kernel() {
    int t = blockIdx.x * blockDim.x + threadIdx.x;
    if (t < Nn) { g_deg[t] = 0; g_cursor[t] = 0; }
    if (t < Gg) { g_gcount[t] = 0; }
}

__global__ void deg_hist_kernel(const int* __restrict__ dst) {
    int e = blockIdx.x * blockDim.x + threadIdx.x;
    if (e < Ee) atomicAdd(&g_deg[dst[e]], 1);
}

__global__ void batch_hist_kernel(const int* __restrict__ batch) {
    int n = blockIdx.x * blockDim.x + threadIdx.x;
    if (n < Nn) atomicAdd(&g_gcount[batch[n]], 1);
}

__global__ void dinv_kernel() {
    int n = blockIdx.x * blockDim.x + threadIdx.x;
    if (n < Nn) g_dinv[n] = rsqrtf((float)(g_deg[n] + 1));  // +1 self loop
}

// single-block exclusive scan (n up to ~100k)
__global__ void scan_excl_kernel(const int* __restrict__ in, int* __restrict__ out, int n) {
    __shared__ int sh[1024];
    int tid = threadIdx.x;
    int carry = 0;
    for (int base = 0; base < n; base += 1024) {
        int v = (base + tid < n) ? in[base + tid] : 0;
        sh[tid] = v;
        __syncthreads();
        #pragma unroll
        for (int off = 1; off < 1024; off <<= 1) {
            int t = (tid >= off) ? sh[tid - off] : 0;
            __syncthreads();
            sh[tid] += t;
            __syncthreads();
        }
        int incl = sh[tid];
        int total = sh[1023];
        if (base + tid < n) out[base + tid] = carry + incl - v;
        carry += total;
        __syncthreads();
    }
    if (tid == 0) out[n] = carry;
}

__global__ void fill_csr_kernel(const int* __restrict__ src, const int* __restrict__ dst) {
    int e = blockIdx.x * blockDim.x + threadIdx.x;
    if (e >= Ee) return;
    int d = dst[e];
    int s = src[e];
    int pos = g_rowoff[d] + atomicAdd(&g_cursor[d], 1);
    EdgeT ed;
    ed.src = s;
    ed.w = g_dinv[s];
    g_edges[pos] = ed;
}

// ---------------- embedding -----------------------------------------------
__global__ void embed_kernel(const float* __restrict__ x,
                             const float* __restrict__ z_embed,
                             const float* __restrict__ ew,
                             const float* __restrict__ eb) {
    int t = blockIdx.x * blockDim.x + threadIdx.x;
    if (t >= Nn * Hh) return;
    int n = t >> 7;
    int j = t & 127;
    int z = (int)x[n * 4];
    float v = z_embed[z * Hh + j];
    v = fmaf(x[n * 4 + 1], ew[j * 3 + 0], v);
    v = fmaf(x[n * 4 + 2], ew[j * 3 + 1], v);
    v = fmaf(x[n * 4 + 3], ew[j * 3 + 2], v);
    g_h[t] = v + eb[j];
}

// ---------------- edge aggregation (warp per dst node) --------------------
__global__ void agg_kernel(const float* __restrict__ cb) {
    int t = blockIdx.x * blockDim.x + threadIdx.x;
    int node = t >> 5;
    int lane = t & 31;
    if (node >= Nn) return;
    const float4* xw4 = (const float4*)g_xw;
    int s = g_rowoff[node];
    int e2 = g_rowoff[node + 1];
    float ax = 0.f, ay = 0.f, az = 0.f, aw = 0.f;
    int e = s;
    for (; e + 2 <= e2; e += 2) {
        EdgeT e0 = g_edges[e];
        EdgeT e1 = g_edges[e + 1];
        float4 v0 = xw4[e0.src * 32 + lane];
        float4 v1 = xw4[e1.src * 32 + lane];
        ax = fmaf(v0.x, e0.w, ax); ay = fmaf(v0.y, e0.w, ay);
        az = fmaf(v0.z, e0.w, az); aw = fmaf(v0.w, e0.w, aw);
        ax = fmaf(v1.x, e1.w, ax); ay = fmaf(v1.y, e1.w, ay);
        az = fmaf(v1.z, e1.w, az); aw = fmaf(v1.w, e1.w, aw);
    }
    if (e < e2) {
        EdgeT e0 = g_edges[e];
        float4 v0 = xw4[e0.src * 32 + lane];
        ax = fmaf(v0.x, e0.w, ax); ay = fmaf(v0.y, e0.w, ay);
        az = fmaf(v0.z, e0.w, az); aw = fmaf(v0.w, e0.w, aw);
    }
    float di = g_dinv[node];
    float4 sv = xw4[node * 32 + lane];
    float4 b = ((const float4*)cb)[lane];
    float4 r;
    r.x = fmaf(ax + sv.x * di, di, b.x);
    r.y = fmaf(ay + sv.y * di, di, b.y);
    r.z = fmaf(az + sv.z * di, di, b.z);
    r.w = fmaf(aw + sv.w * di, di, b.w);
    ((float4*)g_agg)[node * 32 + lane] = r;
}

// ---------------- GraphNorm + swish (block per graph, thread per dim) ------
__global__ void gnorm_kernel(const float* __restrict__ gamma,
                             const float* __restrict__ beta,
                             const float* __restrict__ ms) {
    int g = blockIdx.x;
    int j = threadIdx.x;
    int gs = g_gstart[g];
    int ge = g_gstart[g + 1];
    float cnt = fmaxf((float)(ge - gs), 1.0f);
    float s = 0.f;
    for (int n = gs; n < ge; n++) s += g_agg[n * Hh + j];
    float msj = ms[j] * (s / cnt);
    float vs = 0.f;
    for (int n = gs; n < ge; n++) {
        float d = g_agg[n * Hh + j] - msj;
        vs = fmaf(d, d, vs);
    }
    float rinv = rsqrtf(vs / cnt + 1e-5f);
    float gam = gamma[j] * rinv;
    float bet = beta[j];
    for (int n = gs; n < ge; n++) {
        float d = g_agg[n * Hh + j] - msj;
        float hn = fmaf(gam, d, bet);
        g_agg[n * Hh + j] = hn / (1.0f + __expf(-hn));
    }
}

// ---------------- tiled fp32 GEMM:  C[n, DO] = act(A[n, DI] @ W[DO, DI]^T) --
// ACT: 0 = raw (no bias), 1 = bias+swish, 2 = bias+swish+residual
template <int DI, int ACT>
__global__ void __launch_bounds__(256)
gemm_kernel(const float* __restrict__ A, const float* __restrict__ W,
            const float* __restrict__ bias, const float* __restrict__ res,
            float* __restrict__ C, int nrows, int DO) {
    constexpr int BM = 128, BN = 64, BK = 16;
    __shared__ float As[BK][BM + 4];
    __shared__ float Ws[BK][BN + 4];
    int tid = threadIdx.x;
    int tc = tid & 15;        // 16 col-threads
    int tr = tid >> 4;        // 16 row-threads
    int bm = blockIdx.x * BM;
    int bn = blockIdx.y * BN;

    float acc[8][4];
    #pragma unroll
    for (int i = 0; i < 8; i++)
        #pragma unroll
        for (int j = 0; j < 4; j++) acc[i][j] = 0.f;

    for (int kt = 0; kt < DI; kt += BK) {
        // load A tile [BM x BK]
        #pragma unroll
        for (int i = 0; i < 2; i++) {
            int q = tid + i * 256;      // 0..511 float4s
            int row = q >> 2;
            int kc = (q & 3) << 2;
            float4 v = make_float4(0.f, 0.f, 0.f, 0.f);
            int gr = bm + row;
            if (gr < nrows) v = *(const float4*)(A + (size_t)gr * DI + kt + kc);
            As[kc + 0][row] = v.x; As[kc + 1][row] = v.y;
            As[kc + 2][row] = v.z; As[kc + 3][row] = v.w;
        }
        // load W tile [BN x BK]
        {
            int q = tid;                // 0..255 float4s
            int col = q >> 2;
            int kc = (q & 3) << 2;
            float4 v = *(const float4*)(W + (size_t)(bn + col) * DI + kt + kc);
            Ws[kc + 0][col] = v.x; Ws[kc + 1][col] = v.y;
            Ws[kc + 2][col] = v.z; Ws[kc + 3][col] = v.w;
        }
        __syncthreads();
        #pragma unroll
        for (int k = 0; k < BK; k++) {
            float a[8], w[4];
            #pragma unroll
            for (int i = 0; i < 8; i++) a[i] = As[k][tr * 8 + i];
            #pragma unroll
            for (int j = 0; j < 4; j++) w[j] = Ws[k][tc * 4 + j];
            #pragma unroll
            for (int i = 0; i < 8; i++)
                #pragma unroll
                for (int j = 0; j < 4; j++)
                    acc[i][j] = fmaf(a[i], w[j], acc[i][j]);
        }
        __syncthreads();
    }

    #pragma unroll
    for (int i = 0; i < 8; i++) {
        int row = bm + tr * 8 + i;
        if (row >= nrows) continue;
        #pragma unroll
        for (int j = 0; j < 4; j++) {
            int col = bn + tc * 4 + j;
            float v = acc[i][j];
            if (ACT >= 1) {
                v += bias[col];
                v = v / (1.0f + __expf(-v));   // swish
            }
            if (ACT == 2) v += res[(size_t)row * DO + col];
            C[(size_t)row * DO + col] = v;
        }
    }
}

// ---------------- host launcher -------------------------------------------
extern "C" void kernel_launch(void* const* d_in, const int* in_sizes, int n_in,
                              void* d_out, int out_size) {
    const float* x        = (const float*)d_in[0];    // [N,4]
    const int*   ei       = (const int*)d_in[1];      // [2,E]
    const int*   batch    = (const int*)d_in[2];      // [N]
    const float* z_embed  = (const float*)d_in[3];    // [A,H]
    const float* extra_w  = (const float*)d_in[4];    // [H,3]
    const float* extra_b  = (const float*)d_in[5];    // [H]
    const float* conv_w   = (const float*)d_in[6];    // [L,H,H]
    const float* conv_b   = (const float*)d_in[7];    // [L,H]
    const float* gamma    = (const float*)d_in[8];    // [L,H]
    const float* beta     = (const float*)d_in[9];    // [L,H]
    const float* ms       = (const float*)d_in[10];   // [L,H]
    const float* w1       = (const float*)d_in[11];   // [L,M,H]
    const float* b1       = (const float*)d_in[12];   // [L,M]
    const float* w2       = (const float*)d_in[13];   // [L,H,M]
    const float* b2       = (const float*)d_in[14];   // [L,H]
    float* out = (float*)d_out;

    void* p;
    cudaGetSymbolAddress(&p, g_h);      float* h   = (float*)p;
    cudaGetSymbolAddress(&p, g_xw);     float* xw  = (float*)p;
    cudaGetSymbolAddress(&p, g_agg);    float* agg = (float*)p;
    cudaGetSymbolAddress(&p, g_t);      float* tbuf = (float*)p;
    cudaGetSymbolAddress(&p, g_deg);    int* deg    = (int*)p;
    cudaGetSymbolAddress(&p, g_rowoff); int* rowoff = (int*)p;
    cudaGetSymbolAddress(&p, g_gcount); int* gcount = (int*)p;
    cudaGetSymbolAddress(&p, g_gstart); int* gstart = (int*)p;

    const int* src = ei;
    const int* dst = ei + Ee;

    // ---- per-call graph preprocessing ----
    zero_kernel<<<(Nn + 255) / 256, 256>>>();
    deg_hist_kernel<<<(Ee + 255) / 256, 256>>>(dst);
    batch_hist_kernel<<<(Nn + 255) / 256, 256>>>(batch);
    dinv_kernel<<<(Nn + 255) / 256, 256>>>();
    scan_excl_kernel<<<1, 1024>>>(deg, rowoff, Nn);
    scan_excl_kernel<<<1, 1024>>>(gcount, gstart, Gg);
    fill_csr_kernel<<<(Ee + 255) / 256, 256>>>(src, dst);

    // ---- embedding ----
    embed_kernel<<<(Nn * Hh + 255) / 256, 256>>>(x, z_embed, extra_w, extra_b);

    const int GRID_M = (Nn + 127) / 128;   // 782
    // ---- layers ----
    for (int i = 0; i < Ll; i++) {
        // conv GEMM: xw = h @ conv_w[i]^T (no bias, no act)
        gemm_kernel<128, 0><<<dim3(GRID_M, 2), 256>>>(
            h, conv_w + (size_t)i * Hh * Hh, nullptr, nullptr, xw, Nn, Hh);
        // aggregation + conv bias
        agg_kernel<<<(Nn * 32) / 256, 256>>>(conv_b + (size_t)i * Hh);
        // GraphNorm + swish (in place on agg)
        gnorm_kernel<<<Gg, 128>>>(gamma + (size_t)i * Hh, beta + (size_t)i * Hh,
                                  ms + (size_t)i * Hh);
        // MLP1: t = swish(agg @ w1^T + b1)
        gemm_kernel<128, 1><<<dim3(GRID_M, 4), 256>>>(
            agg, w1 + (size_t)i * Mm * Hh, b1 + (size_t)i * Mm, nullptr, tbuf, Nn, Mm);
        // MLP2: h = swish(t @ w2^T + b2) + h   (last layer writes to d_out)
        float* Cout = (i == Ll - 1) ? out : h;
        gemm_kernel<256, 2><<<dim3(GRID_M, 2), 256>>>(
            tbuf, w2 + (size_t)i * Hh * Mm, b2 + (size_t)i * Hh, h, Cout, Nn, Hh);
    }
}

// round 3
// speedup vs baseline: 1.3684x; 1.3684x over previous
#include <cuda_runtime.h>
#include <cuda_bf16.h>
#include <math.h>
#include <stdint.h>

// Problem constants
constexpr int Nn = 100000;
constexpr int Ee = 1600000;
constexpr int Hh = 128;
constexpr int Mm = 256;
constexpr int Ll = 6;
constexpr int Gg = 512;

// ---------------- scratch (device globals; no allocation allowed) ----------
__device__ float g_h[Nn * Hh];                 // node features / residual (fp32)
__device__ __nv_bfloat16 g_h_hi[Nn * Hh];
__device__ __nv_bfloat16 g_h_lo[Nn * Hh];
__device__ float g_xw[Nn * Hh];                // conv GEMM out (pre-aggregation)
__device__ float g_agg[Nn * Hh];               // aggregated activations
__device__ __nv_bfloat16 g_agg_hi[Nn * Hh];
__device__ __nv_bfloat16 g_agg_lo[Nn * Hh];
__device__ __nv_bfloat16 g_t_hi[Nn * Mm];      // MLP hidden (bf16 split only)
__device__ __nv_bfloat16 g_t_lo[Nn * Mm];
// weight splits
__device__ __nv_bfloat16 g_cw_hi[Ll * Hh * Hh];
__device__ __nv_bfloat16 g_cw_lo[Ll * Hh * Hh];
__device__ __nv_bfloat16 g_w1_hi[Ll * Mm * Hh];
__device__ __nv_bfloat16 g_w1_lo[Ll * Mm * Hh];
__device__ __nv_bfloat16 g_w2_hi[Ll * Hh * Mm];
__device__ __nv_bfloat16 g_w2_lo[Ll * Hh * Mm];
// CSR
__device__ int   g_deg[Nn];
__device__ int   g_cursor[Nn];
__device__ int   g_rowoff[Nn + 1];
__device__ float g_dinv[Nn];
__device__ int   g_gcount[Gg];
__device__ int   g_gstart[Gg + 1];

struct __align__(8) EdgeT { int src; float w; };
__device__ EdgeT g_edges[Ee];

// ================= helpers =================================================
__device__ __forceinline__ uint32_t smem_u32(const void* p) {
    uint32_t a;
    asm("{ .reg .u64 t; cvta.to.shared.u64 t, %1; cvt.u32.u64 %0, t; }"
        : "=r"(a) : "l"(p));
    return a;
}
__device__ __forceinline__ void ldsm_x4(uint32_t* r, uint32_t addr) {
    asm volatile("ldmatrix.sync.aligned.m8n8.x4.shared.b16 {%0,%1,%2,%3}, [%4];"
        : "=r"(r[0]), "=r"(r[1]), "=r"(r[2]), "=r"(r[3]) : "r"(addr));
}
__device__ __forceinline__ void ldsm_x2(uint32_t* r, uint32_t addr) {
    asm volatile("ldmatrix.sync.aligned.m8n8.x2.shared.b16 {%0,%1}, [%2];"
        : "=r"(r[0]), "=r"(r[1]) : "r"(addr));
}
__device__ __forceinline__ void mma16816(float* c, const uint32_t* a, const uint32_t* b) {
    asm volatile(
        "mma.sync.aligned.m16n8k16.row.col.f32.bf16.bf16.f32 "
        "{%0,%1,%2,%3}, {%4,%5,%6,%7}, {%8,%9}, {%0,%1,%2,%3};"
        : "+f"(c[0]), "+f"(c[1]), "+f"(c[2]), "+f"(c[3])
        : "r"(a[0]), "r"(a[1]), "r"(a[2]), "r"(a[3]), "r"(b[0]), "r"(b[1]));
}
__device__ __forceinline__ void split2(float v, __nv_bfloat16& h, __nv_bfloat16& l) {
    h = __float2bfloat16(v);
    l = __float2bfloat16(v - __bfloat162float(h));
}
__device__ __forceinline__ uint32_t pack2(__nv_bfloat16 a, __nv_bfloat16 b) {
    __nv_bfloat162 t;
    t.x = a; t.y = b;
    return *reinterpret_cast<uint32_t*>(&t);
}

// ================= setup kernels ===========================================
__global__ void zero_kernel() {
    int t = blockIdx.x * blockDim.x + threadIdx.x;
    if (t < Nn) { g_deg[t] = 0; g_cursor[t] = 0; }
    if (t < Gg) { g_gcount[t] = 0; }
}
__global__ void deg_hist_kernel(const int* __restrict__ dst) {
    int e = blockIdx.x * blockDim.x + threadIdx.x;
    if (e < Ee) atomicAdd(&g_deg[dst[e]], 1);
}
__global__ void batch_hist_kernel(const int* __restrict__ batch) {
    int n = blockIdx.x * blockDim.x + threadIdx.x;
    if (n < Nn) atomicAdd(&g_gcount[batch[n]], 1);
}
__global__ void dinv_kernel() {
    int n = blockIdx.x * blockDim.x + threadIdx.x;
    if (n < Nn) g_dinv[n] = rsqrtf((float)(g_deg[n] + 1));
}
__global__ void scan_excl_kernel(const int* __restrict__ in, int* __restrict__ out, int n) {
    __shared__ int sh[1024];
    int tid = threadIdx.x;
    int carry = 0;
    for (int base = 0; base < n; base += 1024) {
        int v = (base + tid < n) ? in[base + tid] : 0;
        sh[tid] = v;
        __syncthreads();
        #pragma unroll
        for (int off = 1; off < 1024; off <<= 1) {
            int t = (tid >= off) ? sh[tid - off] : 0;
            __syncthreads();
            sh[tid] += t;
            __syncthreads();
        }
        int incl = sh[tid];
        int total = sh[1023];
        if (base + tid < n) out[base + tid] = carry + incl - v;
        carry += total;
        __syncthreads();
    }
    if (tid == 0) out[n] = carry;
}
__global__ void fill_csr_kernel(const int* __restrict__ src, const int* __restrict__ dst) {
    int e = blockIdx.x * blockDim.x + threadIdx.x;
    if (e >= Ee) return;
    int d = dst[e];
    int s = src[e];
    int pos = g_rowoff[d] + atomicAdd(&g_cursor[d], 1);
    EdgeT ed; ed.src = s; ed.w = g_dinv[s];
    g_edges[pos] = ed;
}
__global__ void split_kernel(const float* __restrict__ in,
                             __nv_bfloat16* __restrict__ hi,
                             __nv_bfloat16* __restrict__ lo, int n) {
    int t = blockIdx.x * blockDim.x + threadIdx.x;
    if (t >= n) return;
    __nv_bfloat16 h, l;
    split2(in[t], h, l);
    hi[t] = h; lo[t] = l;
}

// ================= embedding ===============================================
__global__ void embed_kernel(const float* __restrict__ x,
                             const float* __restrict__ z_embed,
                             const float* __restrict__ ew,
                             const float* __restrict__ eb) {
    int t = blockIdx.x * blockDim.x + threadIdx.x;
    if (t >= Nn * Hh) return;
    int n = t >> 7;
    int j = t & 127;
    int z = (int)x[n * 4];
    float v = z_embed[z * Hh + j];
    v = fmaf(x[n * 4 + 1], ew[j * 3 + 0], v);
    v = fmaf(x[n * 4 + 2], ew[j * 3 + 1], v);
    v = fmaf(x[n * 4 + 3], ew[j * 3 + 2], v);
    v += eb[j];
    g_h[t] = v;
    __nv_bfloat16 h, l;
    split2(v, h, l);
    g_h_hi[t] = h; g_h_lo[t] = l;
}

// ================= edge aggregation (warp per dst node) ====================
__global__ void agg_kernel(const float* __restrict__ cb) {
    int t = blockIdx.x * blockDim.x + threadIdx.x;
    int node = t >> 5;
    int lane = t & 31;
    if (node >= Nn) return;
    const float4* xw4 = (const float4*)g_xw;
    int s = g_rowoff[node];
    int e2 = g_rowoff[node + 1];
    float ax = 0.f, ay = 0.f, az = 0.f, aw = 0.f;
    int e = s;
    for (; e + 2 <= e2; e += 2) {
        EdgeT e0 = g_edges[e];
        EdgeT e1 = g_edges[e + 1];
        float4 v0 = xw4[e0.src * 32 + lane];
        float4 v1 = xw4[e1.src * 32 + lane];
        ax = fmaf(v0.x, e0.w, ax); ay = fmaf(v0.y, e0.w, ay);
        az = fmaf(v0.z, e0.w, az); aw = fmaf(v0.w, e0.w, aw);
        ax = fmaf(v1.x, e1.w, ax); ay = fmaf(v1.y, e1.w, ay);
        az = fmaf(v1.z, e1.w, az); aw = fmaf(v1.w, e1.w, aw);
    }
    if (e < e2) {
        EdgeT e0 = g_edges[e];
        float4 v0 = xw4[e0.src * 32 + lane];
        ax = fmaf(v0.x, e0.w, ax); ay = fmaf(v0.y, e0.w, ay);
        az = fmaf(v0.z, e0.w, az); aw = fmaf(v0.w, e0.w, aw);
    }
    float di = g_dinv[node];
    float4 sv = xw4[node * 32 + lane];
    float4 b = ((const float4*)cb)[lane];
    float4 r;
    r.x = fmaf(ax + sv.x * di, di, b.x);
    r.y = fmaf(ay + sv.y * di, di, b.y);
    r.z = fmaf(az + sv.z * di, di, b.z);
    r.w = fmaf(aw + sv.w * di, di, b.w);
    ((float4*)g_agg)[node * 32 + lane] = r;
}

// ============ GraphNorm + swish, 2-pass (block/graph, thread/dim) ==========
__global__ void gnorm_kernel(const float* __restrict__ gamma,
                             const float* __restrict__ beta,
                             const float* __restrict__ ms) {
    int g = blockIdx.x;
    int j = threadIdx.x;
    int gs = g_gstart[g];
    int ge = g_gstart[g + 1];
    float cnt = fmaxf((float)(ge - gs), 1.0f);
    float s = 0.f, sq = 0.f;
    for (int n = gs; n < ge; n++) {
        float v = g_agg[n * Hh + j];
        s += v;
        sq = fmaf(v, v, sq);
    }
    float mean = s / cnt;
    float msj = ms[j] * mean;
    float var = sq / cnt - 2.0f * msj * mean + msj * msj;
    float rinv = rsqrtf(var + 1e-5f);
    float gam = gamma[j] * rinv;
    float bet = beta[j];
    for (int n = gs; n < ge; n++) {
        float d = g_agg[n * Hh + j] - msj;
        float hn = fmaf(gam, d, bet);
        float sw = hn / (1.0f + __expf(-hn));
        __nv_bfloat16 h, l;
        split2(sw, h, l);
        g_agg_hi[n * Hh + j] = h;
        g_agg_lo[n * Hh + j] = l;
    }
}

// ================= mma.sync GEMM ===========================================
// C[row, DO] = act( A[row, DI] @ W[DO, DI]^T ), bf16 hi/lo 3-term split.
// Block 128x128, 8 warps (2x4), warp tile 64x32, BK=32.
// ACT: 0 conv (fp32 C), 1 mlp1 (bias+swish -> bf16 hi/lo), 2 mlp2 (bias+swish+res).
constexpr int PITCH = 40;   // halves per smem row (80B -> conflict-free ldmatrix)

template <int DI, int ACT>
__global__ void __launch_bounds__(256, 2)
mma_gemm_kernel(const __nv_bfloat16* __restrict__ Ahi, const __nv_bfloat16* __restrict__ Alo,
                const __nv_bfloat16* __restrict__ Bhi, const __nv_bfloat16* __restrict__ Blo,
                const float* __restrict__ bias, const float* __restrict__ res,
                float* __restrict__ Cf,
                __nv_bfloat16* __restrict__ Chi, __nv_bfloat16* __restrict__ Clo,
                int nrows, int DO, int write_hilo) {
    __shared__ __nv_bfloat16 sAhi[128 * PITCH];
    __shared__ __nv_bfloat16 sAlo[128 * PITCH];
    __shared__ __nv_bfloat16 sBhi[128 * PITCH];
    __shared__ __nv_bfloat16 sBlo[128 * PITCH];

    int tid = threadIdx.x;
    int lane = tid & 31;
    int wid = tid >> 5;
    int warp_m = wid & 1;        // 2 warps in M
    int warp_n = wid >> 1;       // 4 warps in N
    int bm = blockIdx.x * 128;
    int bn = blockIdx.y * 128;

    float acc[4][4][4];
    #pragma unroll
    for (int i = 0; i < 4; i++)
        #pragma unroll
        for (int j = 0; j < 4; j++)
            #pragma unroll
            for (int k = 0; k < 4; k++) acc[i][j][k] = 0.f;

    // ldmatrix lane addressing
    int a_row = lane & 15;               // rows 0-15 within 16x16 tile
    int a_col = (lane >> 4) * 8;         // halves
    int b_row = lane & 7;                // n within 8
    int b_col = ((lane >> 3) & 1) * 8;   // k halves (x2: lanes 0-15 used)

    uint32_t uAhi = smem_u32(sAhi) + ((warp_m * 64 + a_row) * PITCH + a_col) * 2;
    uint32_t uAlo = smem_u32(sAlo) + ((warp_m * 64 + a_row) * PITCH + a_col) * 2;
    uint32_t uBhi = smem_u32(sBhi) + ((warp_n * 32 + b_row) * PITCH + b_col) * 2;
    uint32_t uBlo = smem_u32(sBlo) + ((warp_n * 32 + b_row) * PITCH + b_col) * 2;

    for (int kt = 0; kt < DI; kt += 32) {
        // ---- fill tiles: 512 uint4 units per matrix, 2 per thread ----
        #pragma unroll
        for (int u = 0; u < 2; u++) {
            int q = tid + u * 256;           // 0..511
            int r = q >> 2;                  // row 0..127
            int c = (q & 3) * 8;             // half offset
            int so = r * PITCH + c;
            size_t ga = (size_t)(bm + r) * DI + kt + c;
            uint4 vh = make_uint4(0, 0, 0, 0), vl = make_uint4(0, 0, 0, 0);
            if (bm + r < nrows) {
                vh = *(const uint4*)(Ahi + ga);
                vl = *(const uint4*)(Alo + ga);
            }
            *(uint4*)&sAhi[so] = vh;
            *(uint4*)&sAlo[so] = vl;
            size_t gb = (size_t)(bn + r) * DI + kt + c;
            *(uint4*)&sBhi[so] = *(const uint4*)(Bhi + gb);
            *(uint4*)&sBlo[so] = *(const uint4*)(Blo + gb);
        }
        __syncthreads();

        #pragma unroll
        for (int kk = 0; kk < 2; kk++) {       // two k16 steps per BK
            uint32_t aF[4][4], bF[4][2];
            int aoff = kk * 32;                // 16 halves
            int boff = kk * 32;
            // term 1: Ahi * Bhi
            #pragma unroll
            for (int mi = 0; mi < 4; mi++) ldsm_x4(aF[mi], uAhi + mi * (16 * PITCH * 2) + aoff);
            #pragma unroll
            for (int ni = 0; ni < 4; ni++) ldsm_x2(bF[ni], uBhi + ni * (8 * PITCH * 2) + boff);
            #pragma unroll
            for (int mi = 0; mi < 4; mi++)
                #pragma unroll
                for (int ni = 0; ni < 4; ni++) mma16816(acc[mi][ni], aF[mi], bF[ni]);
            // term 2: Ahi * Blo (A reused)
            #pragma unroll
            for (int ni = 0; ni < 4; ni++) ldsm_x2(bF[ni], uBlo + ni * (8 * PITCH * 2) + boff);
            #pragma unroll
            for (int mi = 0; mi < 4; mi++)
                #pragma unroll
                for (int ni = 0; ni < 4; ni++) mma16816(acc[mi][ni], aF[mi], bF[ni]);
            // term 3: Alo * Bhi
            #pragma unroll
            for (int mi = 0; mi < 4; mi++) ldsm_x4(aF[mi], uAlo + mi * (16 * PITCH * 2) + aoff);
            #pragma unroll
            for (int ni = 0; ni < 4; ni++) ldsm_x2(bF[ni], uBhi + ni * (8 * PITCH * 2) + boff);
            #pragma unroll
            for (int mi = 0; mi < 4; mi++)
                #pragma unroll
                for (int ni = 0; ni < 4; ni++) mma16816(acc[mi][ni], aF[mi], bF[ni]);
        }
        __syncthreads();
    }

    // ---- epilogue ----
    int g = lane >> 2;
    int t = lane & 3;
    int row_base = bm + warp_m * 64;
    int col_base = bn + warp_n * 32;
    #pragma unroll
    for (int mi = 0; mi < 4; mi++) {
        #pragma unroll
        for (int ni = 0; ni < 4; ni++) {
            int col = col_base + ni * 8 + t * 2;
            float b0 = 0.f, b1 = 0.f;
            if (ACT >= 1) { b0 = bias[col]; b1 = bias[col + 1]; }
            #pragma unroll
            for (int hf = 0; hf < 2; hf++) {
                int row = row_base + mi * 16 + g + hf * 8;
                if (row >= nrows) continue;
                float v0 = acc[mi][ni][hf * 2 + 0];
                float v1 = acc[mi][ni][hf * 2 + 1];
                if (ACT >= 1) {
                    v0 += b0; v1 += b1;
                    v0 = v0 / (1.0f + __expf(-v0));
                    v1 = v1 / (1.0f + __expf(-v1));
                }
                if (ACT == 2) {
                    float2 rv = *(const float2*)(res + (size_t)row * DO + col);
                    v0 += rv.x; v1 += rv.y;
                }
                if (ACT != 1) {
                    float2 o; o.x = v0; o.y = v1;
                    *(float2*)(Cf + (size_t)row * DO + col) = o;
                }
                if (ACT == 1 || (ACT == 2 && write_hilo)) {
                    __nv_bfloat16 h0, l0, h1, l1;
                    split2(v0, h0, l0);
                    split2(v1, h1, l1);
                    *(uint32_t*)(Chi + (size_t)row * DO + col) = pack2(h0, h1);
                    *(uint32_t*)(Clo + (size_t)row * DO + col) = pack2(l0, l1);
                }
            }
        }
    }
}

// ================= host launcher ===========================================
extern "C" void kernel_launch(void* const* d_in, const int* in_sizes, int n_in,
                              void* d_out, int out_size) {
    const float* x        = (const float*)d_in[0];
    const int*   ei       = (const int*)d_in[1];
    const int*   batch    = (const int*)d_in[2];
    const float* z_embed  = (const float*)d_in[3];
    const float* extra_w  = (const float*)d_in[4];
    const float* extra_b  = (const float*)d_in[5];
    const float* conv_w   = (const float*)d_in[6];
    const float* conv_b   = (const float*)d_in[7];
    const float* gamma    = (const float*)d_in[8];
    const float* beta     = (const float*)d_in[9];
    const float* ms       = (const float*)d_in[10];
    const float* w1       = (const float*)d_in[11];
    const float* b1       = (const float*)d_in[12];
    const float* w2       = (const float*)d_in[13];
    const float* b2       = (const float*)d_in[14];
    float* out = (float*)d_out;

    void* p;
    cudaGetSymbolAddress(&p, g_h);      float* h    = (float*)p;
    cudaGetSymbolAddress(&p, g_h_hi);   __nv_bfloat16* h_hi = (__nv_bfloat16*)p;
    cudaGetSymbolAddress(&p, g_h_lo);   __nv_bfloat16* h_lo = (__nv_bfloat16*)p;
    cudaGetSymbolAddress(&p, g_agg_hi); __nv_bfloat16* a_hi = (__nv_bfloat16*)p;
    cudaGetSymbolAddress(&p, g_agg_lo); __nv_bfloat16* a_lo = (__nv_bfloat16*)p;
    cudaGetSymbolAddress(&p, g_t_hi);   __nv_bfloat16* t_hi = (__nv_bfloat16*)p;
    cudaGetSymbolAddress(&p, g_t_lo);   __nv_bfloat16* t_lo = (__nv_bfloat16*)p;
    cudaGetSymbolAddress(&p, g_xw);     float* xw   = (float*)p;
    cudaGetSymbolAddress(&p, g_cw_hi);  __nv_bfloat16* cwh = (__nv_bfloat16*)p;
    cudaGetSymbolAddress(&p, g_cw_lo);  __nv_bfloat16* cwl = (__nv_bfloat16*)p;
    cudaGetSymbolAddress(&p, g_w1_hi);  __nv_bfloat16* w1h = (__nv_bfloat16*)p;
    cudaGetSymbolAddress(&p, g_w1_lo);  __nv_bfloat16* w1l = (__nv_bfloat16*)p;
    cudaGetSymbolAddress(&p, g_w2_hi);  __nv_bfloat16* w2h = (__nv_bfloat16*)p;
    cudaGetSymbolAddress(&p, g_w2_lo);  __nv_bfloat16* w2l = (__nv_bfloat16*)p;
    cudaGetSymbolAddress(&p, g_deg);    int* deg    = (int*)p;
    cudaGetSymbolAddress(&p, g_rowoff); int* rowoff = (int*)p;
    cudaGetSymbolAddress(&p, g_gcount); int* gcount = (int*)p;
    cudaGetSymbolAddress(&p, g_gstart); int* gstart = (int*)p;

    const int* src = ei;
    const int* dst = ei + Ee;

    // ---- per-call graph preprocessing ----
    zero_kernel<<<(Nn + 255) / 256, 256>>>();
    deg_hist_kernel<<<(Ee + 255) / 256, 256>>>(dst);
    batch_hist_kernel<<<(Nn + 255) / 256, 256>>>(batch);
    dinv_kernel<<<(Nn + 255) / 256, 256>>>();
    scan_excl_kernel<<<1, 1024>>>(deg, rowoff, Nn);
    scan_excl_kernel<<<1, 1024>>>(gcount, gstart, Gg);
    fill_csr_kernel<<<(Ee + 255) / 256, 256>>>(src, dst);

    // ---- weight splits (once per call) ----
    split_kernel<<<(Ll * Hh * Hh + 255) / 256, 256>>>(conv_w, cwh, cwl, Ll * Hh * Hh);
    split_kernel<<<(Ll * Mm * Hh + 255) / 256, 256>>>(w1, w1h, w1l, Ll * Mm * Hh);
    split_kernel<<<(Ll * Hh * Mm + 255) / 256, 256>>>(w2, w2h, w2l, Ll * Hh * Mm);

    // ---- embedding ----
    embed_kernel<<<(Nn * Hh + 255) / 256, 256>>>(x, z_embed, extra_w, extra_b);

    const int GRID_M = (Nn + 127) / 128;   // 782
    for (int i = 0; i < Ll; i++) {
        // conv: xw = h @ conv_w^T (fp32 out)
        mma_gemm_kernel<128, 0><<<dim3(GRID_M, 1), 256>>>(
            h_hi, h_lo, cwh + (size_t)i * Hh * Hh, cwl + (size_t)i * Hh * Hh,
            nullptr, nullptr, xw, nullptr, nullptr, Nn, Hh, 0);
        // aggregation + conv bias
        agg_kernel<<<(Nn * 32) / 256, 256>>>(conv_b + (size_t)i * Hh);
        // GraphNorm + swish -> agg hi/lo
        gnorm_kernel<<<Gg, 128>>>(gamma + (size_t)i * Hh, beta + (size_t)i * Hh,
                                  ms + (size_t)i * Hh);
        // mlp1: t = swish(agg @ w1^T + b1) -> bf16 hi/lo
        mma_gemm_kernel<128, 1><<<dim3(GRID_M, 2), 256>>>(
            a_hi, a_lo, w1h + (size_t)i * Mm * Hh, w1l + (size_t)i * Mm * Hh,
            b1 + (size_t)i * Mm, nullptr, nullptr, t_hi, t_lo, Nn, Mm, 0);
        // mlp2: h = swish(t @ w2^T + b2) + h
        float* Cout = (i == Ll - 1) ? out : h;
        mma_gemm_kernel<256, 2><<<dim3(GRID_M, 1), 256>>>(
            t_hi, t_lo, w2h + (size_t)i * Hh * Mm, w2l + (size_t)i * Hh * Mm,
            b2 + (size_t)i * Hh, h, Cout, h_hi, h_lo, Nn, Hh, (i < Ll - 1) ? 1 : 0);
    }
}

// round 5
// speedup vs baseline: 1.8052x; 1.3192x over previous
#include <cuda_runtime.h>
#include <cuda_bf16.h>
#include <math.h>
#include <stdint.h>

// Problem constants
constexpr int Nn = 100000;
constexpr int Ee = 1600000;
constexpr int Hh = 128;
constexpr int Mm = 256;
constexpr int Ll = 6;
constexpr int Gg = 512;
constexpr int SCAN_BLOCKS = (Nn + 1023) / 1024;   // 98

// ---------------- scratch (device globals) ---------------------------------
__device__ __nv_bfloat16 g_h_hi[Nn * Hh];
__device__ __nv_bfloat16 g_h_lo[Nn * Hh];
__device__ float g_xw[Nn * Hh];                // conv GEMM out (pre-aggregation)
__device__ float g_agg[Nn * Hh];               // aggregated activations
__device__ __nv_bfloat16 g_agg_hi[Nn * Hh];
__device__ __nv_bfloat16 g_agg_lo[Nn * Hh];
__device__ __nv_bfloat16 g_t_hi[Nn * Mm];      // MLP hidden
__device__ __nv_bfloat16 g_t_lo[Nn * Mm];
// weight splits
__device__ __nv_bfloat16 g_cw_hi[Ll * Hh * Hh];
__device__ __nv_bfloat16 g_cw_lo[Ll * Hh * Hh];
__device__ __nv_bfloat16 g_w1_hi[Ll * Mm * Hh];
__device__ __nv_bfloat16 g_w1_lo[Ll * Mm * Hh];
__device__ __nv_bfloat16 g_w2_hi[Ll * Hh * Mm];
__device__ __nv_bfloat16 g_w2_lo[Ll * Hh * Mm];
// CSR
__device__ int   g_deg[Nn];
__device__ int   g_cursor[Nn];
__device__ int   g_rowoff[Nn + 1];
__device__ float g_dinv[Nn];
__device__ int   g_gcount[Gg];
__device__ int   g_gstart[Gg + 1];
__device__ int   g_bsum[SCAN_BLOCKS];

struct __align__(8) EdgeT { int src; float w; };
__device__ EdgeT g_edges[Ee];

// ================= helpers =================================================
__device__ __forceinline__ uint32_t smem_u32(const void* p) {
    uint32_t a;
    asm("{ .reg .u64 t; cvta.to.shared.u64 t, %1; cvt.u32.u64 %0, t; }"
        : "=r"(a) : "l"(p));
    return a;
}
__device__ __forceinline__ void ldsm_x4(uint32_t* r, uint32_t addr) {
    asm volatile("ldmatrix.sync.aligned.m8n8.x4.shared.b16 {%0,%1,%2,%3}, [%4];"
        : "=r"(r[0]), "=r"(r[1]), "=r"(r[2]), "=r"(r[3]) : "r"(addr));
}
__device__ __forceinline__ void ldsm_x2(uint32_t* r, uint32_t addr) {
    asm volatile("ldmatrix.sync.aligned.m8n8.x2.shared.b16 {%0,%1}, [%2];"
        : "=r"(r[0]), "=r"(r[1]) : "r"(addr));
}
__device__ __forceinline__ void mma16816(float* c, const uint32_t* a, const uint32_t* b) {
    asm volatile(
        "mma.sync.aligned.m16n8k16.row.col.f32.bf16.bf16.f32 "
        "{%0,%1,%2,%3}, {%4,%5,%6,%7}, {%8,%9}, {%0,%1,%2,%3};"
        : "+f"(c[0]), "+f"(c[1]), "+f"(c[2]), "+f"(c[3])
        : "r"(a[0]), "r"(a[1]), "r"(a[2]), "r"(a[3]), "r"(b[0]), "r"(b[1]));
}
__device__ __forceinline__ void cp16(uint32_t saddr, const void* gptr, bool pred) {
    int sz = pred ? 16 : 0;
    asm volatile("cp.async.cg.shared.global [%0], [%1], 16, %2;"
        :: "r"(saddr), "l"(gptr), "r"(sz));
}
#define CP_COMMIT() asm volatile("cp.async.commit_group;" ::: "memory")
#define CP_WAIT0()  asm volatile("cp.async.wait_group 0;" ::: "memory")

__device__ __forceinline__ void split2(float v, __nv_bfloat16& h, __nv_bfloat16& l) {
    h = __float2bfloat16(v);
    l = __float2bfloat16(v - __bfloat162float(h));
}
__device__ __forceinline__ uint32_t pack2(__nv_bfloat16 a, __nv_bfloat16 b) {
    __nv_bfloat162 t;
    t.x = a; t.y = b;
    return *reinterpret_cast<uint32_t*>(&t);
}

// ================= setup kernels ===========================================
__global__ void zero_kernel() {
    int t = blockIdx.x * blockDim.x + threadIdx.x;
    if (t < Nn) { g_deg[t] = 0; g_cursor[t] = 0; }
    if (t < Gg) { g_gcount[t] = 0; }
}
// combined degree + batch histogram
__global__ void hist_kernel(const int* __restrict__ dst, const int* __restrict__ batch) {
    int t = blockIdx.x * blockDim.x + threadIdx.x;
    if (t < Ee) atomicAdd(&g_deg[dst[t]], 1);
    if (t < Nn) atomicAdd(&g_gcount[batch[t]], 1);
}
__global__ void dinv_kernel() {
    int n = blockIdx.x * blockDim.x + threadIdx.x;
    if (n < Nn) g_dinv[n] = rsqrtf((float)(g_deg[n] + 1));
}
// multi-block scan: part1 — per-block exclusive scan + block sums
__global__ void scan1_kernel(const int* __restrict__ in, int* __restrict__ out, int n) {
    __shared__ int sh[1024];
    int tid = threadIdx.x;
    int base = blockIdx.x * 1024;
    int v = (base + tid < n) ? in[base + tid] : 0;
    sh[tid] = v;
    __syncthreads();
    #pragma unroll
    for (int off = 1; off < 1024; off <<= 1) {
        int t = (tid >= off) ? sh[tid - off] : 0;
        __syncthreads();
        sh[tid] += t;
        __syncthreads();
    }
    if (base + tid < n) out[base + tid] = sh[tid] - v;
    if (tid == 0) g_bsum[blockIdx.x] = sh[1023];
}
// part2 — scan block sums (serial, tiny), write grand total to out[n]
__global__ void scan2_kernel(int* __restrict__ out, int n, int nblocks) {
    if (threadIdx.x == 0) {
        int acc = 0;
        for (int b = 0; b < nblocks; b++) {
            int v = g_bsum[b];
            g_bsum[b] = acc;
            acc += v;
        }
        out[n] = acc;
    }
}
// part3 — add block offsets
__global__ void scan3_kernel(int* __restrict__ out, int n) {
    int t = blockIdx.x * blockDim.x + threadIdx.x;
    if (t < n) out[t] += g_bsum[blockIdx.x >> 2];   // 256 thr/block: 4 blocks per 1024-chunk
}
// single-block scan for gstart (G=512)
__global__ void scanG_kernel() {
    __shared__ int sh[1024];
    int tid = threadIdx.x;
    int v = (tid < Gg) ? g_gcount[tid] : 0;
    sh[tid] = v;
    __syncthreads();
    #pragma unroll
    for (int off = 1; off < 1024; off <<= 1) {
        int t = (tid >= off) ? sh[tid - off] : 0;
        __syncthreads();
        sh[tid] += t;
        __syncthreads();
    }
    if (tid < Gg) g_gstart[tid] = sh[tid] - v;
    if (tid == 0) g_gstart[Gg] = sh[1023];
}
__global__ void fill_csr_kernel(const int* __restrict__ src, const int* __restrict__ dst) {
    int e = blockIdx.x * blockDim.x + threadIdx.x;
    if (e >= Ee) return;
    int d = dst[e];
    int s = src[e];
    int pos = g_rowoff[d] + atomicAdd(&g_cursor[d], 1);
    EdgeT ed; ed.src = s; ed.w = g_dinv[s];
    g_edges[pos] = ed;
}
// fused weight split (conv_w, w1, w2)
constexpr int CWN = Ll * Hh * Hh;
constexpr int W1N = Ll * Mm * Hh;
constexpr int W2N = Ll * Hh * Mm;
__global__ void split_all_kernel(const float* __restrict__ cw,
                                 const float* __restrict__ w1,
                                 const float* __restrict__ w2) {
    int t = blockIdx.x * blockDim.x + threadIdx.x;
    float v;
    __nv_bfloat16 *hi, *lo;
    int idx;
    if (t < CWN) { idx = t; v = cw[idx]; hi = g_cw_hi; lo = g_cw_lo; }
    else if (t < CWN + W1N) { idx = t - CWN; v = w1[idx]; hi = g_w1_hi; lo = g_w1_lo; }
    else if (t < CWN + W1N + W2N) { idx = t - CWN - W1N; v = w2[idx]; hi = g_w2_hi; lo = g_w2_lo; }
    else return;
    __nv_bfloat16 h, l;
    split2(v, h, l);
    hi[idx] = h; lo[idx] = l;
}

// ================= embedding ===============================================
__global__ void embed_kernel(const float* __restrict__ x,
                             const float* __restrict__ z_embed,
                             const float* __restrict__ ew,
                             const float* __restrict__ eb) {
    int t = blockIdx.x * blockDim.x + threadIdx.x;
    if (t >= Nn * Hh) return;
    int n = t >> 7;
    int j = t & 127;
    int z = (int)x[n * 4];
    float v = z_embed[z * Hh + j];
    v = fmaf(x[n * 4 + 1], ew[j * 3 + 0], v);
    v = fmaf(x[n * 4 + 2], ew[j * 3 + 1], v);
    v = fmaf(x[n * 4 + 3], ew[j * 3 + 2], v);
    v += eb[j];
    __nv_bfloat16 h, l;
    split2(v, h, l);
    g_h_hi[t] = h; g_h_lo[t] = l;
}

// ================= edge aggregation (warp per dst node) ====================
__global__ void agg_kernel(const float* __restrict__ cb) {
    int t = blockIdx.x * blockDim.x + threadIdx.x;
    int node = t >> 5;
    int lane = t & 31;
    if (node >= Nn) return;
    const float4* xw4 = (const float4*)g_xw;
    int s = g_rowoff[node];
    int e2 = g_rowoff[node + 1];
    float ax = 0.f, ay = 0.f, az = 0.f, aw = 0.f;
    int e = s;
    for (; e + 2 <= e2; e += 2) {
        EdgeT e0 = g_edges[e];
        EdgeT e1 = g_edges[e + 1];
        float4 v0 = xw4[e0.src * 32 + lane];
        float4 v1 = xw4[e1.src * 32 + lane];
        ax = fmaf(v0.x, e0.w, ax); ay = fmaf(v0.y, e0.w, ay);
        az = fmaf(v0.z, e0.w, az); aw = fmaf(v0.w, e0.w, aw);
        ax = fmaf(v1.x, e1.w, ax); ay = fmaf(v1.y, e1.w, ay);
        az = fmaf(v1.z, e1.w, az); aw = fmaf(v1.w, e1.w, aw);
    }
    if (e < e2) {
        EdgeT e0 = g_edges[e];
        float4 v0 = xw4[e0.src * 32 + lane];
        ax = fmaf(v0.x, e0.w, ax); ay = fmaf(v0.y, e0.w, ay);
        az = fmaf(v0.z, e0.w, az); aw = fmaf(v0.w, e0.w, aw);
    }
    float di = g_dinv[node];
    float4 sv = xw4[node * 32 + lane];
    float4 b = ((const float4*)cb)[lane];
    float4 r;
    r.x = fmaf(ax + sv.x * di, di, b.x);
    r.y = fmaf(ay + sv.y * di, di, b.y);
    r.z = fmaf(az + sv.z * di, di, b.z);
    r.w = fmaf(aw + sv.w * di, di, b.w);
    ((float4*)g_agg)[node * 32 + lane] = r;
}

// ============ GraphNorm + swish (block/graph, 4-way node parallel) =========
__global__ void __launch_bounds__(512)
gnorm_kernel(const float* __restrict__ gamma,
             const float* __restrict__ beta,
             const float* __restrict__ ms) {
    __shared__ float ssum[4][128];
    __shared__ float ssq[4][128];
    __shared__ float sms[128], sgam[128], sbet[128];
    int g = blockIdx.x;
    int tid = threadIdx.x;
    int j = tid & 127;
    int part = tid >> 7;           // 0..3
    int gs = g_gstart[g];
    int ge = g_gstart[g + 1];
    float s = 0.f, sq = 0.f;
    for (int n = gs + part; n < ge; n += 4) {
        float v = g_agg[n * Hh + j];
        s += v;
        sq = fmaf(v, v, sq);
    }
    ssum[part][j] = s; ssq[part][j] = sq;
    __syncthreads();
    if (part == 0) {
        float S = ssum[0][j] + ssum[1][j] + ssum[2][j] + ssum[3][j];
        float Q = ssq[0][j] + ssq[1][j] + ssq[2][j] + ssq[3][j];
        float cnt = fmaxf((float)(ge - gs), 1.0f);
        float mean = S / cnt;
        float msj = ms[j] * mean;
        float var = Q / cnt - 2.0f * msj * mean + msj * msj;
        float rinv = rsqrtf(var + 1e-5f);
        sms[j] = msj;
        sgam[j] = gamma[j] * rinv;
        sbet[j] = beta[j];
    }
    __syncthreads();
    float msj = sms[j], gam = sgam[j], bet = sbet[j];
    for (int n = gs + part; n < ge; n += 4) {
        float d = g_agg[n * Hh + j] - msj;
        float hn = fmaf(gam, d, bet);
        float sw = hn / (1.0f + __expf(-hn));
        __nv_bfloat16 h, l;
        split2(sw, h, l);
        g_agg_hi[n * Hh + j] = h;
        g_agg_lo[n * Hh + j] = l;
    }
}

// ================= mma.sync GEMM with cp.async =============================
// C[row, DO] = act( A[row, DI] @ W[DO, DI]^T ), bf16 hi/lo 3-term split.
// Block 128x128, 8 warps (2x4), warp tile 64x32, K-chunk 64.
// ACT: 0 conv (fp32 C), 1 mlp1 (bf16 hi/lo), 2 mlp2 (bias+swish+res).
constexpr int PIT = 72;                 // halves per smem row (144B)
constexpr int TILEH = 128 * PIT;        // halves per tile
constexpr int GEMM_SMEM = 4 * TILEH * 2;  // 73728 bytes

template <int DI, int ACT>
__global__ void __launch_bounds__(256, 2)
mma_gemm_kernel(const __nv_bfloat16* __restrict__ Ahi, const __nv_bfloat16* __restrict__ Alo,
                const __nv_bfloat16* __restrict__ Bhi, const __nv_bfloat16* __restrict__ Blo,
                const float* __restrict__ bias,
                const __nv_bfloat16* __restrict__ res_hi, const __nv_bfloat16* __restrict__ res_lo,
                float* __restrict__ Cf,
                __nv_bfloat16* __restrict__ Chi, __nv_bfloat16* __restrict__ Clo,
                int nrows, int DO, int write_hilo, int write_f32) {
    extern __shared__ __nv_bfloat16 sm[];
    uint32_t sbase = smem_u32(sm);
    const uint32_t oAhi = 0, oAlo = TILEH * 2, oBhi = 2 * TILEH * 2, oBlo = 3 * TILEH * 2;

    int tid = threadIdx.x;
    int lane = tid & 31;
    int wid = tid >> 5;
    int warp_m = wid & 1;
    int warp_n = wid >> 1;
    int bm = blockIdx.x * 128;
    int bn = blockIdx.y * 128;

    float acc[4][4][4];
    #pragma unroll
    for (int i = 0; i < 4; i++)
        #pragma unroll
        for (int j = 0; j < 4; j++)
            #pragma unroll
            for (int k = 0; k < 4; k++) acc[i][j][k] = 0.f;

    int a_row = lane & 15;
    int a_col = (lane >> 4) * 8;
    int b_row = lane & 7;
    int b_col = ((lane >> 3) & 1) * 8;
    uint32_t uAhi = sbase + oAhi + ((warp_m * 64 + a_row) * PIT + a_col) * 2;
    uint32_t uAlo = sbase + oAlo + ((warp_m * 64 + a_row) * PIT + a_col) * 2;
    uint32_t uBhi = sbase + oBhi + ((warp_n * 32 + b_row) * PIT + b_col) * 2;
    uint32_t uBlo = sbase + oBlo + ((warp_n * 32 + b_row) * PIT + b_col) * 2;

    constexpr int NCH = DI / 64;
    for (int c = 0; c < NCH; c++) {
        // ---- async loads: per tile 128 rows x 4 uint4; 4 per thread per tile
        #pragma unroll
        for (int u = 0; u < 4; u++) {
            int q = tid + u * 256;        // 0..1023
            int r = q >> 3;
            int cc = (q & 7) * 8;         // half offset within 64
            uint32_t so = (uint32_t)(r * PIT + cc) * 2;
            size_t ga = (size_t)(bm + r) * DI + c * 64 + cc;
            bool av = (bm + r) < nrows;
            cp16(sbase + oAhi + so, Ahi + ga, av);
            cp16(sbase + oAlo + so, Alo + ga, av);
            size_t gb = (size_t)(bn + r) * DI + c * 64 + cc;
            cp16(sbase + oBhi + so, Bhi + gb, true);
            cp16(sbase + oBlo + so, Blo + gb, true);
        }
        CP_COMMIT();
        CP_WAIT0();
        __syncthreads();

        #pragma unroll
        for (int kk = 0; kk < 4; kk++) {
            uint32_t aF[4][4], bh[4][2], bl[4][2];
            int ko = kk * 32;            // bytes (16 halves)
            #pragma unroll
            for (int mi = 0; mi < 4; mi++) ldsm_x4(aF[mi], uAhi + mi * (16 * PIT * 2) + ko);
            #pragma unroll
            for (int ni = 0; ni < 4; ni++) ldsm_x2(bh[ni], uBhi + ni * (8 * PIT * 2) + ko);
            #pragma unroll
            for (int ni = 0; ni < 4; ni++) ldsm_x2(bl[ni], uBlo + ni * (8 * PIT * 2) + ko);
            // term 1: Ahi * Bhi
            #pragma unroll
            for (int mi = 0; mi < 4; mi++)
                #pragma unroll
                for (int ni = 0; ni < 4; ni++) mma16816(acc[mi][ni], aF[mi], bh[ni]);
            // term 2: Ahi * Blo
            #pragma unroll
            for (int mi = 0; mi < 4; mi++)
                #pragma unroll
                for (int ni = 0; ni < 4; ni++) mma16816(acc[mi][ni], aF[mi], bl[ni]);
            // term 3: Alo * Bhi
            #pragma unroll
            for (int mi = 0; mi < 4; mi++) ldsm_x4(aF[mi], uAlo + mi * (16 * PIT * 2) + ko);
            #pragma unroll
            for (int mi = 0; mi < 4; mi++)
                #pragma unroll
                for (int ni = 0; ni < 4; ni++) mma16816(acc[mi][ni], aF[mi], bh[ni]);
        }
        if (c + 1 < NCH) __syncthreads();
    }

    // ---- epilogue ----
    int g = lane >> 2;
    int t4 = lane & 3;
    int row_base = bm + warp_m * 64;
    int col_base = bn + warp_n * 32;
    #pragma unroll
    for (int mi = 0; mi < 4; mi++) {
        #pragma unroll
        for (int ni = 0; ni < 4; ni++) {
            int col = col_base + ni * 8 + t4 * 2;
            float b0 = 0.f, b1 = 0.f;
            if (ACT >= 1) { b0 = bias[col]; b1 = bias[col + 1]; }
            #pragma unroll
            for (int hf = 0; hf < 2; hf++) {
                int row = row_base + mi * 16 + g + hf * 8;
                if (row >= nrows) continue;
                float v0 = acc[mi][ni][hf * 2 + 0];
                float v1 = acc[mi][ni][hf * 2 + 1];
                if (ACT >= 1) {
                    v0 += b0; v1 += b1;
                    v0 = v0 / (1.0f + __expf(-v0));
                    v1 = v1 / (1.0f + __expf(-v1));
                }
                if (ACT == 2) {
                    __nv_bfloat162 rh = *(const __nv_bfloat162*)(res_hi + (size_t)row * DO + col);
                    __nv_bfloat162 rl = *(const __nv_bfloat162*)(res_lo + (size_t)row * DO + col);
                    v0 += __bfloat162float(rh.x) + __bfloat162float(rl.x);
                    v1 += __bfloat162float(rh.y) + __bfloat162float(rl.y);
                }
                if (ACT == 0 || (ACT == 2 && write_f32)) {
                    float2 o; o.x = v0; o.y = v1;
                    *(float2*)(Cf + (size_t)row * DO + col) = o;
                }
                if (ACT == 1 || (ACT == 2 && write_hilo)) {
                    __nv_bfloat16 h0, l0, h1, l1;
                    split2(v0, h0, l0);
                    split2(v1, h1, l1);
                    *(uint32_t*)(Chi + (size_t)row * DO + col) = pack2(h0, h1);
                    *(uint32_t*)(Clo + (size_t)row * DO + col) = pack2(l0, l1);
                }
            }
        }
    }
}

// ================= host launcher ===========================================
extern "C" void kernel_launch(void* const* d_in, const int* in_sizes, int n_in,
                              void* d_out, int out_size) {
    const float* x        = (const float*)d_in[0];
    const int*   ei       = (const int*)d_in[1];
    const int*   batch    = (const int*)d_in[2];
    const float* z_embed  = (const float*)d_in[3];
    const float* extra_w  = (const float*)d_in[4];
    const float* extra_b  = (const float*)d_in[5];
    const float* conv_w   = (const float*)d_in[6];
    const float* conv_b   = (const float*)d_in[7];
    const float* gamma    = (const float*)d_in[8];
    const float* beta     = (const float*)d_in[9];
    const float* ms       = (const float*)d_in[10];
    const float* w1       = (const float*)d_in[11];
    const float* b1       = (const float*)d_in[12];
    const float* w2       = (const float*)d_in[13];
    const float* b2       = (const float*)d_in[14];
    float* out = (float*)d_out;

    void* p;
    cudaGetSymbolAddress(&p, g_h_hi);   __nv_bfloat16* h_hi = (__nv_bfloat16*)p;
    cudaGetSymbolAddress(&p, g_h_lo);   __nv_bfloat16* h_lo = (__nv_bfloat16*)p;
    cudaGetSymbolAddress(&p, g_agg_hi); __nv_bfloat16* a_hi = (__nv_bfloat16*)p;
    cudaGetSymbolAddress(&p, g_agg_lo); __nv_bfloat16* a_lo = (__nv_bfloat16*)p;
    cudaGetSymbolAddress(&p, g_t_hi);   __nv_bfloat16* t_hi = (__nv_bfloat16*)p;
    cudaGetSymbolAddress(&p, g_t_lo);   __nv_bfloat16* t_lo = (__nv_bfloat16*)p;
    cudaGetSymbolAddress(&p, g_xw);     float* xw   = (float*)p;
    cudaGetSymbolAddress(&p, g_cw_hi);  __nv_bfloat16* cwh = (__nv_bfloat16*)p;
    cudaGetSymbolAddress(&p, g_cw_lo);  __nv_bfloat16* cwl = (__nv_bfloat16*)p;
    cudaGetSymbolAddress(&p, g_w1_hi);  __nv_bfloat16* w1h = (__nv_bfloat16*)p;
    cudaGetSymbolAddress(&p, g_w1_lo);  __nv_bfloat16* w1l = (__nv_bfloat16*)p;
    cudaGetSymbolAddress(&p, g_w2_hi);  __nv_bfloat16* w2h = (__nv_bfloat16*)p;
    cudaGetSymbolAddress(&p, g_w2_lo);  __nv_bfloat16* w2l = (__nv_bfloat16*)p;
    cudaGetSymbolAddress(&p, g_deg);    int* deg    = (int*)p;
    cudaGetSymbolAddress(&p, g_rowoff); int* rowoff = (int*)p;

    static bool attr_done = false;
    if (!attr_done) {
        cudaFuncSetAttribute(mma_gemm_kernel<128, 0>,
                             cudaFuncAttributeMaxDynamicSharedMemorySize, GEMM_SMEM);
        cudaFuncSetAttribute(mma_gemm_kernel<128, 1>,
                             cudaFuncAttributeMaxDynamicSharedMemorySize, GEMM_SMEM);
        cudaFuncSetAttribute(mma_gemm_kernel<256, 2>,
                             cudaFuncAttributeMaxDynamicSharedMemorySize, GEMM_SMEM);
        attr_done = true;
    }

    const int* src = ei;
    const int* dst = ei + Ee;

    // ---- per-call graph preprocessing ----
    zero_kernel<<<(Nn + 255) / 256, 256>>>();
    hist_kernel<<<(Ee + 255) / 256, 256>>>(dst, batch);
    dinv_kernel<<<(Nn + 255) / 256, 256>>>();
    scan1_kernel<<<SCAN_BLOCKS, 1024>>>(deg, rowoff, Nn);
    scan2_kernel<<<1, 32>>>(rowoff, Nn, SCAN_BLOCKS);
    scan3_kernel<<<(Nn + 255) / 256, 256>>>(rowoff, Nn);
    scanG_kernel<<<1, 1024>>>();
    fill_csr_kernel<<<(Ee + 255) / 256, 256>>>(src, dst);

    // ---- weight splits + embedding ----
    split_all_kernel<<<(CWN + W1N + W2N + 255) / 256, 256>>>(conv_w, w1, w2);
    embed_kernel<<<(Nn * Hh + 255) / 256, 256>>>(x, z_embed, extra_w, extra_b);

    const int GRID_M = (Nn + 127) / 128;   // 782
    for (int i = 0; i < Ll; i++) {
        // conv: xw = h @ conv_w^T (fp32 out)
        mma_gemm_kernel<128, 0><<<dim3(GRID_M, 1), 256, GEMM_SMEM>>>(
            h_hi, h_lo, cwh + (size_t)i * Hh * Hh, cwl + (size_t)i * Hh * Hh,
            nullptr, nullptr, nullptr, xw, nullptr, nullptr, Nn, Hh, 0, 1);
        // aggregation + conv bias
        agg_kernel<<<(Nn * 32) / 256, 256>>>(conv_b + (size_t)i * Hh);
        // GraphNorm + swish -> agg hi/lo
        gnorm_kernel<<<Gg, 512>>>(gamma + (size_t)i * Hh, beta + (size_t)i * Hh,
                                  ms + (size_t)i * Hh);
        // mlp1: t = swish(agg @ w1^T + b1) -> bf16 hi/lo
        mma_gemm_kernel<128, 1><<<dim3(GRID_M, 2), 256, GEMM_SMEM>>>(
            a_hi, a_lo, w1h + (size_t)i * Mm * Hh, w1l + (size_t)i * Mm * Hh,
            b1 + (size_t)i * Mm, nullptr, nullptr, nullptr, t_hi, t_lo, Nn, Mm, 0, 0);
        // mlp2: h = swish(t @ w2^T + b2) + h
        int last = (i == Ll - 1);
        mma_gemm_kernel<256, 2><<<dim3(GRID_M, 1), 256, GEMM_SMEM>>>(
            t_hi, t_lo, w2h + (size_t)i * Hh * Mm, w2l + (size_t)i * Hh * Mm,
            b2 + (size_t)i * Hh, h_hi, h_lo, last ? out : nullptr, h_hi, h_lo,
            Nn, Hh, last ? 0 : 1, last ? 1 : 0);
    }
}